// round 8
// baseline (speedup 1.0000x reference)
#include <cuda_runtime.h>
#include <math.h>

#define MAXN 100000
#define MAXE 1200000
#define SCAN_B 512
#define MAXBLK 256

// ---- scratch (static __device__, allocation-free; zero-initialized at load) ----
__device__ __align__(16) float g_h[(size_t)MAXN * 64];   // h = x@W (row stride = Do)
__device__ float               g_as[MAXN];               // h @ a_src
__device__ float               g_ad[MAXN];               // h @ a_dst
__device__ __align__(16) float g_x[(size_t)MAXN * 64];   // layer output -> next input
__device__ int                 g_deg[MAXN];              // in-degree (ZERO at call entry)
__device__ int                 g_rowptr[MAXN];           // after scatter: rowptr[n] = end(n)
__device__ int                 g_csrc[MAXE];             // CSR src indices (grouped by dst)
// decoupled-lookback scan state (ZERO flags at call entry)
__device__ volatile int        g_flag[MAXBLK];
__device__ volatile int        g_aggr[MAXBLK];
__device__ volatile int        g_incl[MAXBLK];

__device__ __forceinline__ float lrelu(float x) { return x > 0.f ? x : 0.2f * x; }

// ================= CSR build: 3 kernels =================

// K_a: in-degree histogram (int4-vectorized; g_deg must be zero at entry)
__global__ void hist_k(const int* __restrict__ ei, int E) {
    int i4 = blockIdx.x * blockDim.x + threadIdx.x;
    const int* dst = ei + E;
    int base = i4 * 4;
    if (base + 3 < E) {
        int4 d = *(const int4*)(dst + base);
        atomicAdd(&g_deg[d.x], 1);
        atomicAdd(&g_deg[d.y], 1);
        atomicAdd(&g_deg[d.z], 1);
        atomicAdd(&g_deg[d.w], 1);
    } else {
        for (int i = base; i < E; i++) atomicAdd(&g_deg[dst[i]], 1);
    }
}

// K_b: single-pass exclusive scan of g_deg -> g_rowptr (decoupled lookback).
// Requires all blocks co-resident (196 blocks of 512 on 148 SMs: fine) and
// g_flag zeroed at entry.
__global__ void scan_k(int N) {
    __shared__ int wsum[16];
    __shared__ int s_off;
    int tid = threadIdx.x, b = blockIdx.x;
    int lane = tid & 31, wid = tid >> 5;
    int i = b * SCAN_B + tid;
    int v = (i < N) ? g_deg[i] : 0;

    // warp inclusive scan
    int x = v;
#pragma unroll
    for (int o = 1; o < 32; o <<= 1) {
        int t = __shfl_up_sync(0xffffffffu, x, o);
        if (lane >= o) x += t;
    }
    if (lane == 31) wsum[wid] = x;
    __syncthreads();
    if (wid == 0 && lane < 16) {
        int y = wsum[lane];
#pragma unroll
        for (int o = 1; o < 16; o <<= 1) {
            int t = __shfl_up_sync(0x0000ffffu, y, o);
            if (lane >= o) y += t;
        }
        wsum[lane] = y;
    }
    __syncthreads();
    int incl  = x + (wid > 0 ? wsum[wid - 1] : 0);
    int total = wsum[15];

    if (tid == 0) {
        if (b == 0) {
            g_incl[0] = total;
            __threadfence();
            g_flag[0] = 2;
            s_off = 0;
        } else {
            g_aggr[b] = total;
            __threadfence();
            g_flag[b] = 1;
            int run = 0;
            for (int p = b - 1; p >= 0; p--) {
                int f;
                do { f = g_flag[p]; } while (f == 0);
                if (f == 2) { run += g_incl[p]; break; }
                run += g_aggr[p];
            }
            s_off = run;
            g_incl[b] = run + total;
            __threadfence();
            g_flag[b] = 2;
        }
    }
    __syncthreads();
    if (i < N) g_rowptr[i] = s_off + incl - v;     // exclusive
}

// K_c: scatter edges into CSR slots (int4-vectorized); rowptr[d] -> end(d)
__global__ void scatter_k(const int* __restrict__ ei, int E) {
    int i4 = blockIdx.x * blockDim.x + threadIdx.x;
    int base = i4 * 4;
    if (base + 3 < E) {
        int4 s = *(const int4*)(ei + base);
        int4 d = *(const int4*)(ei + E + base);
        g_csrc[atomicAdd(&g_rowptr[d.x], 1)] = s.x;
        g_csrc[atomicAdd(&g_rowptr[d.y], 1)] = s.y;
        g_csrc[atomicAdd(&g_rowptr[d.z], 1)] = s.z;
        g_csrc[atomicAdd(&g_rowptr[d.w], 1)] = s.w;
    } else {
        for (int i = base; i < E; i++)
            g_csrc[atomicAdd(&g_rowptr[ei[E + i]], 1)] = ei[i];
    }
}

// K_z: restore the zeroed-state invariant for the next call (runs LAST).
__global__ void cleanup(int N) {
    int i = blockIdx.x * blockDim.x + threadIdx.x;
    if (i < N) g_deg[i] = 0;
    if (i < MAXBLK) { g_flag[i] = 0; }
}

// ================= K1: fused GEMM (Din=64) + attention scores =================
// 256 threads (64 x 4); 8 row-groups => 32 rows per block under ONE W smem load.
template <int Do, bool FROMG>
__global__ void gemm_attn(const float* __restrict__ xin, const float* __restrict__ W,
                          const float* __restrict__ a_s, const float* __restrict__ a_d,
                          int N) {
    const int Din = 64;
    const int RG  = 8;
    __shared__ float Ws[Din * Do];
    __shared__ float xs[4][Din];
    __shared__ float s_as[4][2], s_ad[4][2];

    int col = threadIdx.x;
    int r   = threadIdx.y;
    int tid = r * 64 + col;
    for (int i = tid; i < Din * Do; i += 256) Ws[i] = W[i];

    float av = (col < Do) ? a_s[col] : 0.f;
    float dv = (col < Do) ? a_d[col] : 0.f;

    const float* src = FROMG ? g_x : xin;
    int row0 = blockIdx.x * (4 * RG);

#pragma unroll 1
    for (int g = 0; g < RG; g++) {
        int row = row0 + g * 4 + r;
        __syncthreads();
        xs[r][col] = (row < N) ? src[(size_t)row * Din + col] : 0.f;
        __syncthreads();

        float acc = 0.f;
        if (col < Do) {
#pragma unroll
            for (int k = 0; k < Din; k++) acc += xs[r][k] * Ws[k * Do + col];
        }

        float ps = acc * av;
        float pd = acc * dv;
#pragma unroll
        for (int o = 16; o > 0; o >>= 1) {
            ps += __shfl_down_sync(0xffffffffu, ps, o);
            pd += __shfl_down_sync(0xffffffffu, pd, o);
        }
        if ((col & 31) == 0) { s_as[r][col >> 5] = ps; s_ad[r][col >> 5] = pd; }
        __syncthreads();

        if (row < N) {
            if (col < Do) g_h[(size_t)row * Do + col] = acc;
            if (col == 0) {
                g_as[row] = s_as[r][0] + s_as[r][1];
                g_ad[row] = s_ad[r][0] + s_ad[r][1];
            }
        }
    }
}

// ================= K2: softmax + aggregate (warp per node, paired halves) ====
// Softmax shifted by the self-score (shift-invariant; scores O(10), fp32-safe).
// Two 16-lane halves each process one edge at a time: half h handles chunk
// entries j + 16h; lane owns float4 of columns [4*(lane&15) ..]. Halves folded
// via shfl_xor(16) at the end.
// MODE 0: relu(acc/den + b) -> g_x   (Do = 64, GOUT = true)
// MODE 1: log_softmax(acc/den + b) -> out (Do = 40)
template <int Do, int MODE, bool GOUT>
__global__ void agg(const float* __restrict__ b, float* __restrict__ out_arg, int N) {
    const unsigned FULL = 0xffffffffu;
    const int QL = Do / 4;                 // active quad-lanes per half (16 or 10)
    float* out = GOUT ? g_x : out_arg;
    int w    = (blockIdx.x * blockDim.x + threadIdx.x) >> 5;
    int lane = threadIdx.x & 31;
    if (w >= N) return;
    const int n = w;

    int half = lane >> 4;                  // 0/1: which edge of the pair
    int ql   = lane & 15;                  // column group
    bool act = (ql < QL);

    int end   = g_rowptr[n];
    int start = end - g_deg[n];
    float ad_n  = g_ad[n];
    float eself = lrelu(g_as[n] + ad_n);

    float4 acc = make_float4(0.f, 0.f, 0.f, 0.f);
    if (half == 0 && act)
        acc = *(const float4*)(g_h + (size_t)n * Do + 4 * ql);   // self (ex = 1)
    float den_p = (lane == 0) ? 1.f : 0.f;

    for (int base = start; base < end; base += 32) {
        int i = base + lane;
        int   s = 0;
        float ex = 0.f;
        if (i < end) {
            s  = g_csrc[i];
            ex = __expf(lrelu(g_as[s] + ad_n) - eself);
        }
        den_p += ex;

        int cnt  = min(32, end - base);
        int trip = min(cnt, 16);
        for (int j = 0; j < trip; j++) {
            int   idx = j + (half << 4);
            float ej  = __shfl_sync(FULL, ex, idx);
            int   sj  = __shfl_sync(FULL, s,  idx);
            if (act && ej > 0.f) {
                float4 hv = *(const float4*)(g_h + (size_t)sj * Do + 4 * ql);
                acc.x += ej * hv.x; acc.y += ej * hv.y;
                acc.z += ej * hv.z; acc.w += ej * hv.w;
            }
        }
    }

    // fold the two halves (lanes < 16 end with the full sum)
    acc.x += __shfl_xor_sync(FULL, acc.x, 16);
    acc.y += __shfl_xor_sync(FULL, acc.y, 16);
    acc.z += __shfl_xor_sync(FULL, acc.z, 16);
    acc.w += __shfl_xor_sync(FULL, acc.w, 16);
#pragma unroll
    for (int o = 16; o > 0; o >>= 1)
        den_p += __shfl_xor_sync(FULL, den_p, o);
    float inv = 1.f / den_p;

    if (MODE == 0) {
        if (lane < 16) {
            float4 bv = *(const float4*)(b + 4 * lane);
            float4 o2;
            o2.x = fmaxf(acc.x * inv + bv.x, 0.f);
            o2.y = fmaxf(acc.y * inv + bv.y, 0.f);
            o2.z = fmaxf(acc.z * inv + bv.z, 0.f);
            o2.w = fmaxf(acc.w * inv + bv.w, 0.f);
            *(float4*)(out + (size_t)n * 64 + 4 * lane) = o2;
        }
    } else {
        bool mine = (lane < QL);           // lanes 0..9 hold cols 4l..4l+3
        float v0 = mine ? (acc.x * inv + b[4 * lane])     : -INFINITY;
        float v1 = mine ? (acc.y * inv + b[4 * lane + 1]) : -INFINITY;
        float v2 = mine ? (acc.z * inv + b[4 * lane + 2]) : -INFINITY;
        float v3 = mine ? (acc.w * inv + b[4 * lane + 3]) : -INFINITY;
        float mx = fmaxf(fmaxf(v0, v1), fmaxf(v2, v3));
#pragma unroll
        for (int o = 16; o > 0; o >>= 1)
            mx = fmaxf(mx, __shfl_xor_sync(FULL, mx, o));
        float sum = mine ? (expf(v0 - mx) + expf(v1 - mx) + expf(v2 - mx) + expf(v3 - mx)) : 0.f;
#pragma unroll
        for (int o = 16; o > 0; o >>= 1)
            sum += __shfl_xor_sync(FULL, sum, o);
        float ls = mx + logf(sum);
        if (mine) {
            out[(size_t)n * 40 + 4 * lane]     = v0 - ls;
            out[(size_t)n * 40 + 4 * lane + 1] = v1 - ls;
            out[(size_t)n * 40 + 4 * lane + 2] = v2 - ls;
            out[(size_t)n * 40 + 4 * lane + 3] = v3 - ls;
        }
    }
}

extern "C" void kernel_launch(void* const* d_in, const int* in_sizes, int n_in,
                              void* d_out, int out_size) {
    const int N = in_sizes[0] / 64;
    const int E = in_sizes[1] / 2;
    const float* x  = (const float*)d_in[0];
    const int*   ei = (const int*)d_in[1];     // int32 (JAX downcasts int64)

    const int TB = 256;
    int nblk  = (N + TB - 1) / TB;
    int e4blk = ((E + 3) / 4 + TB - 1) / TB;
    int sblk  = (N + SCAN_B - 1) / SCAN_B;     // 196 blocks, all co-resident
    dim3 gblk(64, 4);
    int gemm_grid = (N + 31) / 32;
    int agg_grid  = (N + 7) / 8;

    // ---- CSR build (3 kernels; relies on zeroed g_deg/g_flag invariant) ----
    hist_k<<<e4blk, TB>>>(ei, E);
    scan_k<<<sblk, SCAN_B>>>(N);
    scatter_k<<<e4blk, TB>>>(ei, E);

    // ---------- layer 0 ----------
    gemm_attn<64, false><<<gemm_grid, gblk>>>(x, (const float*)d_in[2],
                                              (const float*)d_in[3], (const float*)d_in[4], N);
    agg<64, 0, true><<<agg_grid, TB>>>((const float*)d_in[5], nullptr, N);

    // ---------- layer 1 ----------
    gemm_attn<64, true><<<gemm_grid, gblk>>>(nullptr, (const float*)d_in[6],
                                             (const float*)d_in[7], (const float*)d_in[8], N);
    agg<64, 0, true><<<agg_grid, TB>>>((const float*)d_in[9], nullptr, N);

    // ---------- layer 2 ----------
    gemm_attn<40, true><<<gemm_grid, gblk>>>(nullptr, (const float*)d_in[10],
                                             (const float*)d_in[11], (const float*)d_in[12], N);
    agg<40, 1, false><<<agg_grid, TB>>>((const float*)d_in[13], (float*)d_out, N);

    // ---- restore zeroed-state invariant for next call ----
    cleanup<<<nblk, TB>>>(N);
}

// round 10
// speedup vs baseline: 1.6732x; 1.6732x over previous
#include <cuda_runtime.h>
#include <math.h>

#define MAXN 100000
#define MAXE 1200000
#define SCAN_B 512
#define MAXBLK 256

// ---- scratch (static __device__, allocation-free; zero-initialized at load) ----
__device__ __align__(16) float g_h[(size_t)MAXN * 64];   // h = x@W (row stride = Do)
__device__ float               g_as[MAXN];               // h @ a_src
__device__ float               g_ad[MAXN];               // h @ a_dst
__device__ __align__(16) float g_x[(size_t)MAXN * 64];   // layer output -> next input
__device__ int                 g_deg[MAXN];              // in-degree (ZERO at call entry)
__device__ int                 g_rowptr[MAXN];           // after scatter: rowptr[n] = end(n)
__device__ int                 g_csrc[MAXE];             // CSR src indices (grouped by dst)
// decoupled-lookback scan state (ZERO flags at call entry)
__device__ volatile int        g_flag[MAXBLK];
__device__ volatile int        g_aggr[MAXBLK];
__device__ volatile int        g_incl[MAXBLK];

__device__ __forceinline__ float lrelu(float x) { return x > 0.f ? x : 0.2f * x; }

// ================= CSR build: 3 kernels =================

__global__ void hist_k(const int* __restrict__ ei, int E) {
    int i4 = blockIdx.x * blockDim.x + threadIdx.x;
    const int* dst = ei + E;
    int base = i4 * 4;
    if (base + 3 < E) {
        int4 d = *(const int4*)(dst + base);
        atomicAdd(&g_deg[d.x], 1);
        atomicAdd(&g_deg[d.y], 1);
        atomicAdd(&g_deg[d.z], 1);
        atomicAdd(&g_deg[d.w], 1);
    } else {
        for (int i = base; i < E; i++) atomicAdd(&g_deg[dst[i]], 1);
    }
}

// single-pass exclusive scan (decoupled lookback); g_flag zero at entry
__global__ void scan_k(int N) {
    __shared__ int wsum[16];
    __shared__ int s_off;
    int tid = threadIdx.x, b = blockIdx.x;
    int lane = tid & 31, wid = tid >> 5;
    int i = b * SCAN_B + tid;
    int v = (i < N) ? g_deg[i] : 0;

    int x = v;
#pragma unroll
    for (int o = 1; o < 32; o <<= 1) {
        int t = __shfl_up_sync(0xffffffffu, x, o);
        if (lane >= o) x += t;
    }
    if (lane == 31) wsum[wid] = x;
    __syncthreads();
    if (wid == 0 && lane < 16) {
        int y = wsum[lane];
#pragma unroll
        for (int o = 1; o < 16; o <<= 1) {
            int t = __shfl_up_sync(0x0000ffffu, y, o);
            if (lane >= o) y += t;
        }
        wsum[lane] = y;
    }
    __syncthreads();
    int incl  = x + (wid > 0 ? wsum[wid - 1] : 0);
    int total = wsum[15];

    if (tid == 0) {
        if (b == 0) {
            g_incl[0] = total;
            __threadfence();
            g_flag[0] = 2;
            s_off = 0;
        } else {
            g_aggr[b] = total;
            __threadfence();
            g_flag[b] = 1;
            int run = 0;
            for (int p = b - 1; p >= 0; p--) {
                int f;
                do { f = g_flag[p]; } while (f == 0);
                if (f == 2) { run += g_incl[p]; break; }
                run += g_aggr[p];
            }
            s_off = run;
            g_incl[b] = run + total;
            __threadfence();
            g_flag[b] = 2;
        }
    }
    __syncthreads();
    if (i < N) g_rowptr[i] = s_off + incl - v;     // exclusive
}

__global__ void scatter_k(const int* __restrict__ ei, int E) {
    int i4 = blockIdx.x * blockDim.x + threadIdx.x;
    int base = i4 * 4;
    if (base + 3 < E) {
        int4 s = *(const int4*)(ei + base);
        int4 d = *(const int4*)(ei + E + base);
        g_csrc[atomicAdd(&g_rowptr[d.x], 1)] = s.x;
        g_csrc[atomicAdd(&g_rowptr[d.y], 1)] = s.y;
        g_csrc[atomicAdd(&g_rowptr[d.z], 1)] = s.z;
        g_csrc[atomicAdd(&g_rowptr[d.w], 1)] = s.w;
    } else {
        for (int i = base; i < E; i++)
            g_csrc[atomicAdd(&g_rowptr[ei[E + i]], 1)] = ei[i];
    }
}

// restore zeroed-state invariant for the next call (runs LAST)
__global__ void cleanup(int N) {
    int i = blockIdx.x * blockDim.x + threadIdx.x;
    if (i < N) g_deg[i] = 0;
    if (i < MAXBLK) g_flag[i] = 0;
}

// ================= K1: register-tiled GEMM + attention scores =================
// 64x64 output tile, 256 threads, 4x4 accumulators per thread.
// As[k][row] stride 68 (=17*4: 16B-aligned rows AND bank rotation), Bs[k][col].
// Per k-step: 2x LDS.128 + 16 FFMA.
template <int Do, bool FROMG>
__global__ void gemm_attn(const float* __restrict__ xin, const float* __restrict__ W,
                          const float* __restrict__ a_s, const float* __restrict__ a_d,
                          int N) {
    const int Din = 64;
    __shared__ float As[Din][68];      // [k][row]; stride 68 keeps float4 alignment
    __shared__ float Bs[Din][64];      // [k][col] (zero-padded beyond Do)

    int t  = threadIdx.x;              // 0..255
    int tx = t & 15;                   // col group
    int ty = t >> 4;                   // row group
    int rowbase = blockIdx.x * 64;

    const float* src = FROMG ? g_x : xin;

    // load x tile (transposed into As)
    {
        int r0 = t >> 4;               // 0..15
        int k4 = (t & 15) * 4;
#pragma unroll
        for (int q = 0; q < 4; q++) {
            int r = r0 + q * 16;
            int row = rowbase + r;
            float4 x4 = (row < N) ? *(const float4*)(src + (size_t)row * Din + k4)
                                  : make_float4(0.f, 0.f, 0.f, 0.f);
            As[k4 + 0][r] = x4.x;
            As[k4 + 1][r] = x4.y;
            As[k4 + 2][r] = x4.z;
            As[k4 + 3][r] = x4.w;
        }
    }
    // load W tile
    {
        int kk = t >> 4;
        int c4 = (t & 15) * 4;
#pragma unroll
        for (int q = 0; q < 4; q++) {
            int k = kk + q * 16;
            float4 w4 = (c4 < Do) ? *(const float4*)(W + (size_t)k * Do + c4)
                                  : make_float4(0.f, 0.f, 0.f, 0.f);
            *(float4*)&Bs[k][c4] = w4;
        }
    }
    __syncthreads();

    float acc[4][4] = {};
#pragma unroll 8
    for (int k = 0; k < Din; k++) {
        float4 a  = *(const float4*)&As[k][ty * 4];
        float4 bb = *(const float4*)&Bs[k][tx * 4];
        acc[0][0] += a.x * bb.x; acc[0][1] += a.x * bb.y; acc[0][2] += a.x * bb.z; acc[0][3] += a.x * bb.w;
        acc[1][0] += a.y * bb.x; acc[1][1] += a.y * bb.y; acc[1][2] += a.y * bb.z; acc[1][3] += a.y * bb.w;
        acc[2][0] += a.z * bb.x; acc[2][1] += a.z * bb.y; acc[2][2] += a.z * bb.z; acc[2][3] += a.z * bb.w;
        acc[3][0] += a.w * bb.x; acc[3][1] += a.w * bb.y; acc[3][2] += a.w * bb.z; acc[3][3] += a.w * bb.w;
    }

    // attention-vector fragments for this thread's 4 columns
    int c4 = tx * 4;
    float4 av = (c4 < Do) ? *(const float4*)(a_s + c4) : make_float4(0.f, 0.f, 0.f, 0.f);
    float4 dv = (c4 < Do) ? *(const float4*)(a_d + c4) : make_float4(0.f, 0.f, 0.f, 0.f);

#pragma unroll
    for (int i = 0; i < 4; i++) {
        int row = rowbase + ty * 4 + i;
        float ps = acc[i][0] * av.x + acc[i][1] * av.y + acc[i][2] * av.z + acc[i][3] * av.w;
        float pd = acc[i][0] * dv.x + acc[i][1] * dv.y + acc[i][2] * dv.z + acc[i][3] * dv.w;
#pragma unroll
        for (int o = 8; o > 0; o >>= 1) {
            ps += __shfl_xor_sync(0xffffffffu, ps, o);
            pd += __shfl_xor_sync(0xffffffffu, pd, o);
        }
        if (row < N) {
            if (c4 < Do)
                *(float4*)(g_h + (size_t)row * Do + c4) =
                    make_float4(acc[i][0], acc[i][1], acc[i][2], acc[i][3]);
            if (tx == 0) {
                g_as[row] = ps;
                g_ad[row] = pd;
            }
        }
    }
}

// ================= K2: softmax + aggregate (warp per node, float2 lanes) =====
// Shift by self-score (softmax shift-invariant; scores O(10), fp32-safe).
// MODE 0: relu(acc/den + b) -> g_x (Do=64, GOUT=true); MODE 1: log_softmax -> out.
template <int Do, int MODE, bool GOUT>
__global__ void agg(const float* __restrict__ b, float* __restrict__ out_arg, int N) {
    const unsigned FULL = 0xffffffffu;
    float* out = GOUT ? g_x : out_arg;
    int w    = (blockIdx.x * blockDim.x + threadIdx.x) >> 5;
    int lane = threadIdx.x & 31;
    if (w >= N) return;
    const int n = w;

    int end   = g_rowptr[n];
    int start = end - g_deg[n];
    float ad_n  = g_ad[n];
    float eself = lrelu(g_as[n] + ad_n);

    const int HL = Do / 2;
    bool act = (lane < HL);
    float2 acc = act ? *(const float2*)(g_h + (size_t)n * Do + 2 * lane)
                     : make_float2(0.f, 0.f);            // self contribution (ex=1)
    float den_p = (lane == 0) ? 1.f : 0.f;

    for (int base = start; base < end; base += 32) {
        int i = base + lane;
        int   s = 0;
        float ex = 0.f;
        if (i < end) {
            s  = g_csrc[i];
            ex = __expf(lrelu(g_as[s] + ad_n) - eself);
        }
        den_p += ex;

        int cnt = min(32, end - base);
        int j = 0;
        for (; j + 4 <= cnt; j += 4) {
            int   s0 = __shfl_sync(FULL, s, j),     s1 = __shfl_sync(FULL, s, j + 1);
            int   s2 = __shfl_sync(FULL, s, j + 2), s3 = __shfl_sync(FULL, s, j + 3);
            float e0 = __shfl_sync(FULL, ex, j),     e1 = __shfl_sync(FULL, ex, j + 1);
            float e2 = __shfl_sync(FULL, ex, j + 2), e3 = __shfl_sync(FULL, ex, j + 3);
            if (act) {
                float2 h0 = *(const float2*)(g_h + (size_t)s0 * Do + 2 * lane);
                float2 h1 = *(const float2*)(g_h + (size_t)s1 * Do + 2 * lane);
                float2 h2 = *(const float2*)(g_h + (size_t)s2 * Do + 2 * lane);
                float2 h3 = *(const float2*)(g_h + (size_t)s3 * Do + 2 * lane);
                acc.x += e0 * h0.x; acc.y += e0 * h0.y;
                acc.x += e1 * h1.x; acc.y += e1 * h1.y;
                acc.x += e2 * h2.x; acc.y += e2 * h2.y;
                acc.x += e3 * h3.x; acc.y += e3 * h3.y;
            }
        }
        for (; j < cnt; j++) {
            int   sj = __shfl_sync(FULL, s, j);
            float ej = __shfl_sync(FULL, ex, j);
            if (act) {
                float2 hj = *(const float2*)(g_h + (size_t)sj * Do + 2 * lane);
                acc.x += ej * hj.x; acc.y += ej * hj.y;
            }
        }
    }
#pragma unroll
    for (int o = 16; o > 0; o >>= 1)
        den_p += __shfl_xor_sync(FULL, den_p, o);
    float inv = 1.f / den_p;

    if (MODE == 0) {
        float2 bv = *(const float2*)(b + 2 * lane);
        float2 o2;
        o2.x = fmaxf(acc.x * inv + bv.x, 0.f);
        o2.y = fmaxf(acc.y * inv + bv.y, 0.f);
        *(float2*)(out + (size_t)n * 64 + 2 * lane) = o2;
    } else {
        float v0 = act ? (acc.x * inv + b[2 * lane])     : -INFINITY;
        float v1 = act ? (acc.y * inv + b[2 * lane + 1]) : -INFINITY;
        float mx = fmaxf(v0, v1);
#pragma unroll
        for (int o = 16; o > 0; o >>= 1)
            mx = fmaxf(mx, __shfl_xor_sync(FULL, mx, o));
        float sum = act ? (expf(v0 - mx) + expf(v1 - mx)) : 0.f;
#pragma unroll
        for (int o = 16; o > 0; o >>= 1)
            sum += __shfl_xor_sync(FULL, sum, o);
        float ls = mx + logf(sum);
        if (act) {
            out[(size_t)n * 40 + 2 * lane]     = v0 - ls;
            out[(size_t)n * 40 + 2 * lane + 1] = v1 - ls;
        }
    }
}

extern "C" void kernel_launch(void* const* d_in, const int* in_sizes, int n_in,
                              void* d_out, int out_size) {
    const int N = in_sizes[0] / 64;
    const int E = in_sizes[1] / 2;
    const float* x  = (const float*)d_in[0];
    const int*   ei = (const int*)d_in[1];     // int32 (JAX downcasts int64)

    const int TB = 256;
    int nblk  = (N + TB - 1) / TB;
    int e4blk = ((E + 3) / 4 + TB - 1) / TB;
    int sblk  = (N + SCAN_B - 1) / SCAN_B;
    int gemm_grid = (N + 63) / 64;
    int agg_grid  = (N + 7) / 8;

    // ---- CSR build ----
    hist_k<<<e4blk, TB>>>(ei, E);
    scan_k<<<sblk, SCAN_B>>>(N);
    scatter_k<<<e4blk, TB>>>(ei, E);

    // ---------- layer 0 ----------
    gemm_attn<64, false><<<gemm_grid, TB>>>(x, (const float*)d_in[2],
                                            (const float*)d_in[3], (const float*)d_in[4], N);
    agg<64, 0, true><<<agg_grid, TB>>>((const float*)d_in[5], nullptr, N);

    // ---------- layer 1 ----------
    gemm_attn<64, true><<<gemm_grid, TB>>>(nullptr, (const float*)d_in[6],
                                           (const float*)d_in[7], (const float*)d_in[8], N);
    agg<64, 0, true><<<agg_grid, TB>>>((const float*)d_in[9], nullptr, N);

    // ---------- layer 2 ----------
    gemm_attn<40, true><<<gemm_grid, TB>>>(nullptr, (const float*)d_in[10],
                                           (const float*)d_in[11], (const float*)d_in[12], N);
    agg<40, 1, false><<<agg_grid, TB>>>((const float*)d_in[13], (float*)d_out, N);

    // ---- restore zeroed-state invariant for next call ----
    cleanup<<<nblk, TB>>>(N);
}